// round 15
// baseline (speedup 1.0000x reference)
#include <cuda_runtime.h>
#include <cuda_fp16.h>
#include <math.h>
#include <stdint.h>

// ---------------- problem constants ----------------
#define BB   8
#define SS   1024
#define INF_ 256
#define DD   512
#define HH   8
#define LL   2
#define MM   64
#define DK   64
#define FF_  2048
#define BS   (BB*SS)          // 8192 rows
#define EPS  1e-5f
#define NQKV 1536

// ---------------- scratch ----------------
__device__ float  g_x   [BS*DD];          // residual stream (fp32)
__device__ __half g_qkv16[3*BS*DD];       // q/k/v (B,H,S,DK) fp16
__device__ __half g_h16 [BS*DD];          // LN out / attn out (fp16 A operand)
__device__ __half g_in16[BS*INF_];
__device__ __half g_ff16[BS*FF_];
__device__ __half g_wi16[INF_*DD];        // transposed [N,K] fp16 weights
__device__ __half g_wqkv16[LL*NQKV*DD];   // concatenated [Wq;Wk;Wv]^T per layer
__device__ __half g_wo16[LL*DD*DD];
__device__ __half g_w116[LL*DD*FF_];
__device__ __half g_w216[LL*FF_*DD];
__device__ float  g_bqkv[LL*NQKV];
__device__ float  g_pe  [SS*DD];          // precomputed sinusoidal PE (2 MB)

// ---------------- mma.sync helpers ----------------
__device__ __forceinline__ void cp_async16(uint32_t dst, const void* src) {
    asm volatile("cp.async.ca.shared.global [%0], [%1], 16;" :: "r"(dst), "l"(src) : "memory");
}
__device__ __forceinline__ void cp_commit() {
    asm volatile("cp.async.commit_group;" ::: "memory");
}
template<int N>
__device__ __forceinline__ void cp_wait() {
    asm volatile("cp.async.wait_group %0;" :: "n"(N) : "memory");
}
__device__ __forceinline__ void ldmx4(uint32_t& r0, uint32_t& r1, uint32_t& r2, uint32_t& r3, uint32_t addr) {
    asm volatile("ldmatrix.sync.aligned.m8n8.x4.shared.b16 {%0,%1,%2,%3}, [%4];"
                 : "=r"(r0), "=r"(r1), "=r"(r2), "=r"(r3) : "r"(addr));
}
__device__ __forceinline__ void ldmx4t(uint32_t& r0, uint32_t& r1, uint32_t& r2, uint32_t& r3, uint32_t addr) {
    asm volatile("ldmatrix.sync.aligned.m8n8.x4.trans.shared.b16 {%0,%1,%2,%3}, [%4];"
                 : "=r"(r0), "=r"(r1), "=r"(r2), "=r"(r3) : "r"(addr));
}
__device__ __forceinline__ void mma16816(float* c, const uint32_t* a, const uint32_t* b) {
    asm volatile("mma.sync.aligned.m16n8k16.row.col.f32.f16.f16.f32 "
                 "{%0,%1,%2,%3}, {%4,%5,%6,%7}, {%8,%9}, {%0,%1,%2,%3};"
                 : "+f"(c[0]), "+f"(c[1]), "+f"(c[2]), "+f"(c[3])
                 : "r"(a[0]), "r"(a[1]), "r"(a[2]), "r"(a[3]), "r"(b[0]), "r"(b[1]));
}

// fast exp2 via FMA-pipe polynomial; valid for t <= 0
__device__ __forceinline__ float exp2p(float t) {
    t = fmaxf(t, -126.f);
    float z = t + 12582912.f;
    float f = t - (z - 12582912.f);
    float p = 0.00961804886f;
    p = fmaf(p, f, 0.0555041086f);
    p = fmaf(p, f, 0.2402265069f);
    p = fmaf(p, f, 0.6931471806f);
    p = fmaf(p, f, 1.0f);
    return __int_as_float(__float_as_int(p) + (__float_as_int(z) << 23));
}
__device__ __forceinline__ uint32_t f2h2(float a, float b) {
    __half2 h = __floats2half2_rn(a, b);
    return *(uint32_t*)&h;
}

// ================= fused prep kernel =================
#define PR_CONV_END 256
#define PR_WIN_END  (PR_CONV_END + 128)
#define PR_QKV_END  (PR_WIN_END + 1536)
#define PR_WO_END   (PR_QKV_END + 512)
#define PR_W1_END   (PR_WO_END + 2048)
#define PR_W2_END   (PR_W1_END + 2048)
#define PR_BIAS_END (PR_W2_END + 12)
#define PR_PE_END   (PR_BIAS_END + 1024)

__global__ void prep_kernel(const float* __restrict__ inputs, const float* __restrict__ W_in,
                            const float* __restrict__ Wq, const float* __restrict__ Wk,
                            const float* __restrict__ Wv, const float* __restrict__ Wo,
                            const float* __restrict__ W1, const float* __restrict__ W2,
                            const float* __restrict__ bq, const float* __restrict__ bk,
                            const float* __restrict__ bv,
                            __half* __restrict__ in16, __half* __restrict__ wi16,
                            __half* __restrict__ wqkv, __half* __restrict__ wo16,
                            __half* __restrict__ w116, __half* __restrict__ w216,
                            float* __restrict__ bqkv, float* __restrict__ pe)
{
    __shared__ float t[32][33];
    const int blk = blockIdx.x, tid = threadIdx.x;

    if (blk < PR_CONV_END) {
        const int base4 = blk * 2048 + tid;          // float4 index
#pragma unroll
        for (int j = 0; j < 8; j++) {
            float4 v = *(const float4*)(inputs + (size_t)(base4 + j * 256) * 4);
            uint32_t lo = f2h2(v.x, v.y), hi = f2h2(v.z, v.w);
            *(uint2*)(in16 + (size_t)(base4 + j * 256) * 4) = make_uint2(lo, hi);
        }
        return;
    }
    if (blk >= PR_BIAS_END) {
        const int p = (blk - PR_BIAS_END) * 256 + tid;
        const int s = p / (DD / 2), ce2 = p % (DD / 2);
        float div = __expf(-(float)(2 * ce2) * (9.210340371976184f / (float)DD));
        float sn, cs;
        __sincosf((float)s * div, &sn, &cs);
        *(float2*)(pe + (size_t)s * DD + 2 * ce2) = make_float2(sn, cs);
        return;
    }
    if (blk >= PR_W2_END) {
        const int idx = (blk - PR_W2_END) * 256 + tid;
        if (idx < LL * NQKV) {
            const int l = idx / NQKV, c = idx % NQKV;
            float v = (c < 512) ? bq[l * 512 + c]
                    : (c < 1024) ? bk[l * 512 + c - 512]
                                 : bv[l * 512 + c - 1024];
            bqkv[idx] = v;
        }
        return;
    }

    const float* src; __half* dst; int K, N, tile;
    if (blk < PR_WIN_END) {
        tile = blk - PR_CONV_END; K = INF_; N = DD; src = W_in; dst = wi16;
    } else if (blk < PR_QKV_END) {
        int r = blk - PR_WIN_END;
        int l = r / 768, r2 = r % 768, w = r2 >> 8;
        tile = r2 & 255; K = DD; N = DD;
        src = ((w == 0) ? Wq : (w == 1) ? Wk : Wv) + (size_t)l * DD * DD;
        dst = wqkv + (size_t)l * NQKV * DD + (size_t)w * DD * DD;
    } else if (blk < PR_WO_END) {
        int r = blk - PR_QKV_END;
        int l = r >> 8; tile = r & 255; K = DD; N = DD;
        src = Wo + (size_t)l * DD * DD; dst = wo16 + (size_t)l * DD * DD;
    } else if (blk < PR_W1_END) {
        int r = blk - PR_WO_END;
        int l = r >> 10; tile = r & 1023; K = DD; N = FF_;
        src = W1 + (size_t)l * DD * FF_; dst = w116 + (size_t)l * DD * FF_;
    } else {
        int r = blk - PR_W1_END;
        int l = r >> 10; tile = r & 1023; K = FF_; N = DD;
        src = W2 + (size_t)l * FF_ * DD; dst = w216 + (size_t)l * FF_ * DD;
    }

    const int tiles_x = N >> 5;
    const int k0 = (tile / tiles_x) << 5, n0 = (tile % tiles_x) << 5;
    const int x = tid & 31, y = tid >> 5;
#pragma unroll
    for (int i = 0; i < 32; i += 8) t[y + i][x] = src[(size_t)(k0 + y + i) * N + n0 + x];
    __syncthreads();
#pragma unroll
    for (int i = 0; i < 32; i += 8)
        dst[(size_t)(n0 + y + i) * K + k0 + x] = __float2half(t[x][y + i]);
}

// ===== HMMA fp16 GEMM: 128x128 CTA, 4 warps (warp 64x64), 3-stage, 3 CTAs/SM =====
#define BM 128
#define BN 128
#define LDH 40
#define GEMM_SMEM (3 * (BM + BN) * LDH * 2)   // 61440 B dynamic; x3 CTAs = 184 KB

// OUT_MODE: 0 = fp32 row-major; 2 = fp16 row-major; 3 = QKV scatter (B,H,S,DK) x3
template<int OUT_MODE, bool RELU, bool ADD_PE, bool HAS_RES>
__global__ __launch_bounds__(128, 3)
void gemm16(const __half* __restrict__ A, const __half* __restrict__ Bt,
            const float* __restrict__ bias, const float* __restrict__ resid,
            float* __restrict__ Cf, __half* __restrict__ C16, int K, int N, float os_q,
            const int* __restrict__ lengths)
{
    extern __shared__ __align__(16) __half sm16[];
    const uint32_t sA = (uint32_t)__cvta_generic_to_shared(sm16);
    const uint32_t sB = sA + 3 * BM * LDH * 2;

    const int tid  = threadIdx.x;
    const int lane = tid & 31, wid = tid >> 5;
    const int wr = wid >> 1, wc = wid & 1;          // 2 x 2 warps, warp tile 64x64
    const int r0 = blockIdx.y * BM, n0 = blockIdx.x * BN;

    // QKV: skip fully-masked K/V tiles (outputs never read by attention).
    if (OUT_MODE == 3) {
        if (n0 >= 512) {
            const int bI = r0 >> 10, s0 = r0 & (SS - 1);
            if (s0 >= lengths[bI]) return;
        }
    }

    float acc[4][8][4];
#pragma unroll
    for (int i = 0; i < 4; i++)
#pragma unroll
        for (int j = 0; j < 8; j++)
#pragma unroll
            for (int k = 0; k < 4; k++) acc[i][j][k] = 0.f;

    const int T = K >> 5;

#define LOADT(buf, k0)                                                        \
    do {                                                                      \
        _Pragma("unroll")                                                     \
        for (int i = 0; i < 4; i++) {                                         \
            int c_ = tid + i * 128;                                           \
            int row = c_ >> 2, cc = c_ & 3;                                   \
            uint32_t d = sA + ((buf) * BM * LDH + row * LDH + cc * 8) * 2;    \
            cp_async16(d, A + (size_t)(r0 + row) * K + (k0) + cc * 8);        \
        }                                                                     \
        _Pragma("unroll")                                                     \
        for (int i = 0; i < 4; i++) {                                         \
            int c_ = tid + i * 128;                                           \
            int row = c_ >> 2, cc = c_ & 3;                                   \
            uint32_t d = sB + ((buf) * BN * LDH + row * LDH + cc * 8) * 2;    \
            cp_async16(d, Bt + (size_t)(n0 + row) * K + (k0) + cc * 8);       \
        }                                                                     \
    } while (0)

    LOADT(0, 0);  cp_commit();
    LOADT(1, 32); cp_commit();

    const int lrow = lane & 15, lcol = (lane >> 4) * 8;
    const int bg = lane >> 3, br = lane & 7;
    const int brow = ((bg >> 1) * 8) + br, bcol = (bg & 1) * 8;

    for (int t = 0; t < T; t++) {
        if (t == T - 1) cp_wait<0>(); else cp_wait<1>();
        __syncthreads();

        if (t + 2 < T) { LOADT((t + 2) % 3, (t + 2) << 5); cp_commit(); }

        const int cur = t % 3;
#pragma unroll
        for (int ks = 0; ks < 2; ks++) {
            uint32_t af[4][4];
#pragma unroll
            for (int mt = 0; mt < 4; mt++) {
                uint32_t addr = sA + (cur * BM * LDH +
                    (wr * 64 + mt * 16 + lrow) * LDH + ks * 16 + lcol) * 2;
                ldmx4(af[mt][0], af[mt][1], af[mt][2], af[mt][3], addr);
            }
            uint32_t bf[8][2];
#pragma unroll
            for (int np = 0; np < 4; np++) {
                uint32_t addr = sB + (cur * BN * LDH +
                    (wc * 64 + np * 16 + brow) * LDH + ks * 16 + bcol) * 2;
                uint32_t q0, q1, q2, q3;
                ldmx4(q0, q1, q2, q3, addr);
                bf[np * 2][0] = q0; bf[np * 2][1] = q1;
                bf[np * 2 + 1][0] = q2; bf[np * 2 + 1][1] = q3;
            }
#pragma unroll
            for (int mt = 0; mt < 4; mt++)
#pragma unroll
                for (int nt = 0; nt < 8; nt++)
                    mma16816(acc[mt][nt], af[mt], bf[nt]);
        }
    }

    // ---------------- epilogue ----------------
    float* pe = nullptr;
    if (ADD_PE) { asm("cvta.global.u64 %0, %1;" : "=l"(pe) : "l"((void*)g_pe)); }

#pragma unroll
    for (int mt = 0; mt < 4; mt++) {
#pragma unroll
        for (int nt = 0; nt < 8; nt++) {
#pragma unroll
            for (int half_m = 0; half_m < 2; half_m++) {
                const int m   = r0 + wr * 64 + mt * 16 + (lane >> 2) + half_m * 8;
                const int col = n0 + wc * 64 + nt * 8 + 2 * (lane & 3);
                float v0 = acc[mt][nt][half_m * 2 + 0] + bias[col];
                float v1 = acc[mt][nt][half_m * 2 + 1] + bias[col + 1];
                if (RELU) { v0 = fmaxf(v0, 0.f); v1 = fmaxf(v1, 0.f); }
                const int s = m & (SS - 1);
                if (ADD_PE) {
                    float2 p2 = *(const float2*)(pe + (size_t)s * DD + col);
                    v0 += p2.x;
                    v1 += p2.y;
                }
                if (HAS_RES) {
                    v0 += resid[(size_t)m * N + col];
                    v1 += resid[(size_t)m * N + col + 1];
                }
                if (OUT_MODE == 0) {
                    *(float2*)(Cf + (size_t)m * N + col) = make_float2(v0, v1);
                } else if (OUT_MODE == 2) {
                    *(__half2*)(C16 + (size_t)m * N + col) = __floats2half2_rn(v0, v1);
                } else {   // QKV scatter
                    const int sec = col >> 9, cs = col & 511;
                    const float sc = (sec == 0) ? os_q : 1.f;
                    v0 *= sc; v1 *= sc;
                    const int bI = m >> 10;
                    const int hh = cs >> 6, dk = cs & (DK - 1);
                    __half* dst = C16 + (size_t)sec * (BS * DD) +
                                  (((size_t)(bI * HH + hh)) * SS + s) * DK + dk;
                    *(__half2*)dst = __floats2half2_rn(v0, v1);
                }
            }
        }
    }
#undef LOADT
}

// ================= LayerNorm (2 rows / 256-thread block, float4) =================
__device__ __forceinline__ float half_block_sum(float v, int half, int w4)
{
    __shared__ float red[2][4];
    const int lane = threadIdx.x & 31;
#pragma unroll
    for (int o = 16; o; o >>= 1) v += __shfl_xor_sync(0xffffffffu, v, o);
    if (lane == 0) red[half][w4] = v;
    __syncthreads();
    float s = red[half][0] + red[half][1] + red[half][2] + red[half][3];
    __syncthreads();
    return s;
}

template<bool H16>
__global__ void ln_kernel(const float* __restrict__ x, const float* __restrict__ g,
                          const float* __restrict__ be, float* __restrict__ yf,
                          __half* __restrict__ yh)
{
    const int half = threadIdx.x >> 7;
    const int t    = threadIdx.x & 127;
    const int w4   = (threadIdx.x >> 5) & 3;
    const int row  = blockIdx.x * 2 + half;

    const float4 v = *(const float4*)(x + (size_t)row * DD + t * 4);
    float mean = half_block_sum(v.x + v.y + v.z + v.w, half, w4) * (1.0f / DD);
    float d0 = v.x - mean, d1 = v.y - mean, d2 = v.z - mean, d3 = v.w - mean;
    float var = half_block_sum(d0 * d0 + d1 * d1 + d2 * d2 + d3 * d3, half, w4) * (1.0f / DD);
    float rstd = rsqrtf(var + EPS);

    const float4 gv = *(const float4*)(g  + t * 4);
    const float4 bv = *(const float4*)(be + t * 4);
    float o0 = d0 * rstd * gv.x + bv.x;
    float o1 = d1 * rstd * gv.y + bv.y;
    float o2 = d2 * rstd * gv.z + bv.z;
    float o3 = d3 * rstd * gv.w + bv.w;

    if (H16) {
        uint32_t lo = f2h2(o0, o1), hi = f2h2(o2, o3);
        *(uint2*)(yh + (size_t)row * DD + t * 4) = make_uint2(lo, hi);
    } else {
        *(float4*)(yf + (size_t)row * DD + t * 4) = make_float4(o0, o1, o2, o3);
    }
}

// ================= fused HMMA flash attention =================
#define PITCH 72
#define ATT_SMEM (512 + 128*PITCH*2 + 2*64*PITCH*2 + 2*64*PITCH*2)   // 55808

__global__ __launch_bounds__(256, 2)
void attn_mma(const __half* __restrict__ Qg_, const __half* __restrict__ Kg_,
              const __half* __restrict__ Vg_, const float* __restrict__ rb,
              const int* __restrict__ lengths, __half* __restrict__ out)
{
    extern __shared__ __align__(16) char smem_raw[];
    float*  bias_s = (float*)smem_raw;
    __half* Qs = (__half*)(smem_raw + 512);
    __half* Ks = (__half*)(smem_raw + 512 + 18432);
    __half* Vs = (__half*)(smem_raw + 512 + 36864);

    const int tid = threadIdx.x, lane = tid & 31, wr = tid >> 5;
    const int blk = blockIdx.x;
    const int qt = blk & 7, bh = blk >> 3;
    const int h = bh & (HH - 1), b = bh >> 3;
    const int q0 = qt * 128;
    const int len = lengths[b];
    const int nc = (len + 63) >> 6;

    if (tid < 127) bias_s[tid] = rb[h * 127 + tid] * 1.44269504f;

    const __half* Qg = Qg_ + ((size_t)bh * SS + q0) * DK;
    const __half* Kg = Kg_ + (size_t)bh * SS * DK;
    const __half* Vg = Vg_ + (size_t)bh * SS * DK;

#pragma unroll
    for (int i = 0; i < 4; i++) {
        int idx = tid + i * 256; int row = idx >> 3, c = idx & 7;
        cp_async16((uint32_t)__cvta_generic_to_shared(Qs + row * PITCH + c * 8),
                   Qg + (size_t)row * DK + c * 8);
    }
#pragma unroll
    for (int i = 0; i < 2; i++) {
        int idx = tid + i * 256; int row = idx >> 3, c = idx & 7;
        cp_async16((uint32_t)__cvta_generic_to_shared(Ks + row * PITCH + c * 8),
                   Kg + (size_t)row * DK + c * 8);
        cp_async16((uint32_t)__cvta_generic_to_shared(Vs + row * PITCH + c * 8),
                   Vg + (size_t)row * DK + c * 8);
    }
    cp_commit();

    float m0 = -1e30f, m1 = -1e30f, l0 = 0.f, l1 = 0.f;
    float oacc[8][4];
#pragma unroll
    for (int i = 0; i < 8; i++)
#pragma unroll
        for (int j = 0; j < 4; j++) oacc[i][j] = 0.f;
    uint32_t aQ[4][4];

    const int r = lane >> 2;
    const int qg0 = q0 + wr * 16 + r;
    const int qg1 = qg0 + 8;

    for (int cc = 0; cc < nc; cc++) {
        const int buf = cc & 1;
        if (cc + 1 < nc) {
            const int nb = buf ^ 1;
#pragma unroll
            for (int i = 0; i < 2; i++) {
                int idx = tid + i * 256; int row = idx >> 3, c = idx & 7;
                cp_async16((uint32_t)__cvta_generic_to_shared(Ks + nb * 64 * PITCH + row * PITCH + c * 8),
                           Kg + (size_t)((cc + 1) * 64 + row) * DK + c * 8);
                cp_async16((uint32_t)__cvta_generic_to_shared(Vs + nb * 64 * PITCH + row * PITCH + c * 8),
                           Vg + (size_t)((cc + 1) * 64 + row) * DK + c * 8);
            }
            cp_commit();
            cp_wait<1>();
        } else {
            cp_wait<0>();
        }
        __syncthreads();

        if (cc == 0) {
#pragma unroll
            for (int ks = 0; ks < 4; ks++) {
                const __half* p = Qs + (wr * 16 + ((lane >> 3) & 1) * 8 + (lane & 7)) * PITCH
                                  + ks * 16 + (lane >> 4) * 8;
                ldmx4(aQ[ks][0], aQ[ks][1], aQ[ks][2], aQ[ks][3],
                      (uint32_t)__cvta_generic_to_shared(p));
            }
        }

        const __half* kb = Ks + buf * 64 * PITCH;
        float sacc[8][4];
#pragma unroll
        for (int i = 0; i < 8; i++)
#pragma unroll
            for (int j = 0; j < 4; j++) sacc[i][j] = 0.f;
        const int g = lane >> 3, gi = lane & 7;
#pragma unroll
        for (int ks = 0; ks < 4; ks++) {
            uint32_t bK[8][2];
#pragma unroll
            for (int np = 0; np < 4; np++) {
                const __half* p = kb + (np * 16 + ((g >> 1) << 3) + gi) * PITCH
                                  + ks * 16 + ((g & 1) << 3);
                uint32_t t0, t1, t2, t3;
                ldmx4(t0, t1, t2, t3, (uint32_t)__cvta_generic_to_shared(p));
                bK[2 * np][0] = t0; bK[2 * np][1] = t1;
                bK[2 * np + 1][0] = t2; bK[2 * np + 1][1] = t3;
            }
#pragma unroll
            for (int nt = 0; nt < 8; nt++) mma16816(sacc[nt], aQ[ks], bK[nt]);
        }

        // ----- bias + mask fixup: full chunks skip the mask entirely -----
        const int kb0 = cc * 64;
        const bool full = (kb0 + 64 <= len);   // uniform across CTA
        float mc0 = -1e30f, mc1 = -1e30f;
        if (full) {
#pragma unroll
            for (int nt = 0; nt < 8; nt++) {
                const int k0i = kb0 + nt * 8 + 2 * (lane & 3);
#pragma unroll
                for (int e = 0; e < 4; e++) {
                    const int kk = k0i + (e & 1);
                    const int qq = (e < 2) ? qg0 : qg1;
                    int rel = min(63, max(-63, qq - kk)) + 63;
                    float val = sacc[nt][e] + bias_s[rel];
                    sacc[nt][e] = val;
                    if (e < 2) mc0 = fmaxf(mc0, val); else mc1 = fmaxf(mc1, val);
                }
            }
        } else {
#pragma unroll
            for (int nt = 0; nt < 8; nt++) {
                const int k0i = kb0 + nt * 8 + 2 * (lane & 3);
#pragma unroll
                for (int e = 0; e < 4; e++) {
                    const int kk = k0i + (e & 1);
                    const int qq = (e < 2) ? qg0 : qg1;
                    int rel = min(63, max(-63, qq - kk)) + 63;
                    float val = sacc[nt][e] + bias_s[rel];
                    if (kk >= len) val = -1e30f;
                    sacc[nt][e] = val;
                    if (e < 2) mc0 = fmaxf(mc0, val); else mc1 = fmaxf(mc1, val);
                }
            }
        }
        mc0 = fmaxf(mc0, __shfl_xor_sync(0xffffffffu, mc0, 1));
        mc0 = fmaxf(mc0, __shfl_xor_sync(0xffffffffu, mc0, 2));
        mc1 = fmaxf(mc1, __shfl_xor_sync(0xffffffffu, mc1, 1));
        mc1 = fmaxf(mc1, __shfl_xor_sync(0xffffffffu, mc1, 2));
        const float mn0 = fmaxf(m0, mc0), mn1 = fmaxf(m1, mc1);
        const float al0 = exp2p(m0 - mn0), al1 = exp2p(m1 - mn1);
        m0 = mn0; m1 = mn1;

        float ps0 = 0.f, ps1 = 0.f;
        uint32_t aP[4][4];
#pragma unroll
        for (int nt = 0; nt < 8; nt++) {
            float p0 = exp2p(sacc[nt][0] - mn0);
            float p1 = exp2p(sacc[nt][1] - mn0);
            float p2 = exp2p(sacc[nt][2] - mn1);
            float p3 = exp2p(sacc[nt][3] - mn1);
            ps0 += p0 + p1; ps1 += p2 + p3;
            uint32_t lo = f2h2(p0, p1), hi = f2h2(p2, p3);
            if ((nt & 1) == 0) { aP[nt >> 1][0] = lo; aP[nt >> 1][1] = hi; }
            else               { aP[nt >> 1][2] = lo; aP[nt >> 1][3] = hi; }
        }
        ps0 += __shfl_xor_sync(0xffffffffu, ps0, 1);
        ps0 += __shfl_xor_sync(0xffffffffu, ps0, 2);
        ps1 += __shfl_xor_sync(0xffffffffu, ps1, 1);
        ps1 += __shfl_xor_sync(0xffffffffu, ps1, 2);
        l0 = l0 * al0 + ps0;
        l1 = l1 * al1 + ps1;
#pragma unroll
        for (int nt = 0; nt < 8; nt++) {
            oacc[nt][0] *= al0; oacc[nt][1] *= al0;
            oacc[nt][2] *= al1; oacc[nt][3] *= al1;
        }

        const __half* vb = Vs + buf * 64 * PITCH;
#pragma unroll
        for (int kc = 0; kc < 4; kc++) {
            uint32_t bV[8][2];
#pragma unroll
            for (int np = 0; np < 4; np++) {
                const __half* p = vb + (kc * 16 + ((g & 1) << 3) + gi) * PITCH
                                  + np * 16 + ((g >> 1) << 3);
                uint32_t t0, t1, t2, t3;
                ldmx4t(t0, t1, t2, t3, (uint32_t)__cvta_generic_to_shared(p));
                bV[2 * np][0] = t0; bV[2 * np][1] = t1;
                bV[2 * np + 1][0] = t2; bV[2 * np + 1][1] = t3;
            }
#pragma unroll
            for (int nt = 0; nt < 8; nt++) mma16816(oacc[nt], aP[kc], bV[nt]);
        }
        __syncthreads();
    }

    const float inv0 = 1.f / l0, inv1 = 1.f / l1;
    __half* o0p = out + ((size_t)(b * SS + qg0)) * DD + h * DK + 2 * (lane & 3);
    __half* o1p = out + ((size_t)(b * SS + qg1)) * DD + h * DK + 2 * (lane & 3);
#pragma unroll
    for (int nt = 0; nt < 8; nt++) {
        *(__half2*)(o0p + nt * 8) = __floats2half2_rn(oacc[nt][0] * inv0, oacc[nt][1] * inv0);
        *(__half2*)(o1p + nt * 8) = __floats2half2_rn(oacc[nt][2] * inv1, oacc[nt][3] * inv1);
    }
}

// ================= host orchestration =================
#define G_PROJ gemm16<0, false, true,  false>
#define G_RES  gemm16<0, false, false, true >
#define G_QKV  gemm16<3, false, false, false>
#define G_FF1  gemm16<2, true,  false, false>

extern "C" void kernel_launch(void* const* d_in, const int* in_sizes, int n_in,
                              void* d_out, int out_size)
{
    const float* inputs  = (const float*)d_in[0];
    const int*   lengths = (const int*)  d_in[1];
    const float* W_in    = (const float*)d_in[2];
    const float* b_in    = (const float*)d_in[3];
    const float* Wq      = (const float*)d_in[4];
    const float* bq      = (const float*)d_in[5];
    const float* Wk      = (const float*)d_in[6];
    const float* bk      = (const float*)d_in[7];
    const float* Wv      = (const float*)d_in[8];
    const float* bv      = (const float*)d_in[9];
    const float* Wo      = (const float*)d_in[10];
    const float* bo      = (const float*)d_in[11];
    const float* rel_b   = (const float*)d_in[12];
    const float* W1      = (const float*)d_in[13];
    const float* b1      = (const float*)d_in[14];
    const float* W2      = (const float*)d_in[15];
    const float* b2      = (const float*)d_in[16];
    const float* g1      = (const float*)d_in[17];
    const float* be1     = (const float*)d_in[18];
    const float* g2      = (const float*)d_in[19];
    const float* be2     = (const float*)d_in[20];
    const float* gf      = (const float*)d_in[21];
    const float* bef     = (const float*)d_in[22];

    float *x, *bqkv, *pe;
    __half *qkv16, *h16, *in16, *ff16, *wi16, *wqkv16, *wo16, *w116, *w216;
    cudaGetSymbolAddress((void**)&x,      g_x);
    cudaGetSymbolAddress((void**)&qkv16,  g_qkv16);
    cudaGetSymbolAddress((void**)&h16,    g_h16);
    cudaGetSymbolAddress((void**)&in16,   g_in16);
    cudaGetSymbolAddress((void**)&ff16,   g_ff16);
    cudaGetSymbolAddress((void**)&wi16,   g_wi16);
    cudaGetSymbolAddress((void**)&wqkv16, g_wqkv16);
    cudaGetSymbolAddress((void**)&wo16,   g_wo16);
    cudaGetSymbolAddress((void**)&w116,   g_w116);
    cudaGetSymbolAddress((void**)&w216,   g_w216);
    cudaGetSymbolAddress((void**)&bqkv,   g_bqkv);
    cudaGetSymbolAddress((void**)&pe,     g_pe);

    cudaFuncSetAttribute(attn_mma, cudaFuncAttributeMaxDynamicSharedMemorySize, ATT_SMEM);
    cudaFuncSetAttribute(G_PROJ, cudaFuncAttributeMaxDynamicSharedMemorySize, GEMM_SMEM);
    cudaFuncSetAttribute(G_RES,  cudaFuncAttributeMaxDynamicSharedMemorySize, GEMM_SMEM);
    cudaFuncSetAttribute(G_QKV,  cudaFuncAttributeMaxDynamicSharedMemorySize, GEMM_SMEM);
    cudaFuncSetAttribute(G_FF1,  cudaFuncAttributeMaxDynamicSharedMemorySize, GEMM_SMEM);

    prep_kernel<<<PR_PE_END, 256>>>(inputs, W_in, Wq, Wk, Wv, Wo, W1, W2, bq, bk, bv,
                                    in16, wi16, wqkv16, wo16, w116, w216, bqkv, pe);

    const dim3 gD(DD / BN,   BS / BM);    // (4, 64)
    const dim3 gQ(NQKV / BN, BS / BM);    // (12, 64)
    const dim3 gF1(FF_ / BN, BS / BM);    // (16, 64)
    const float QSCALE = 0.125f * 1.44269504f;

    __half* q16 = qkv16;
    __half* k16 = qkv16 + (size_t)BS * DD;
    __half* v16 = qkv16 + 2 * (size_t)BS * DD;

    G_PROJ<<<gD, 128, GEMM_SMEM>>>(in16, wi16, b_in, nullptr, x, nullptr, INF_, DD, 1.0f, nullptr);

    for (int l = 0; l < LL; l++) {
        const __half* wqkv = wqkv16 + (size_t)l * NQKV * DD;
        const __half* wo = wo16 + (size_t)l * DD * DD;
        const __half* w1 = w116 + (size_t)l * DD * FF_;
        const __half* w2 = w216 + (size_t)l * FF_ * DD;

        ln_kernel<true><<<BS / 2, 256>>>(x, g1 + l * DD, be1 + l * DD, nullptr, h16);
        G_QKV<<<gQ, 128, GEMM_SMEM>>>(h16, wqkv, bqkv + l * NQKV, nullptr,
                                      nullptr, qkv16, DD, NQKV, QSCALE, lengths);

        attn_mma<<<BB * HH * (SS / 128), 256, ATT_SMEM>>>(q16, k16, v16,
                                                          rel_b + (size_t)l * HH * (2 * MM - 1),
                                                          lengths, h16);

        G_RES<<<gD, 128, GEMM_SMEM>>>(h16, wo, bo + l * DD, x, x, nullptr, DD, DD, 1.0f, nullptr);

        ln_kernel<true><<<BS / 2, 256>>>(x, g2 + l * DD, be2 + l * DD, nullptr, h16);
        G_FF1<<<gF1, 128, GEMM_SMEM>>>(h16, w1, b1 + l * FF_, nullptr,
                                       nullptr, ff16, DD, FF_, 1.0f, nullptr);
        G_RES<<<gD, 128, GEMM_SMEM>>>(ff16, w2, b2 + l * DD, x, x, nullptr, FF_, DD, 1.0f, nullptr);
    }

    ln_kernel<false><<<BS / 2, 256>>>(x, gf, bef, (float*)d_out, nullptr);
}

// round 16
// speedup vs baseline: 1.0888x; 1.0888x over previous
#include <cuda_runtime.h>
#include <cuda_fp16.h>
#include <math.h>
#include <stdint.h>

// ---------------- problem constants ----------------
#define BB   8
#define SS   1024
#define INF_ 256
#define DD   512
#define HH   8
#define LL   2
#define MM   64
#define DK   64
#define FF_  2048
#define BS   (BB*SS)          // 8192 rows
#define EPS  1e-5f
#define NQKV 1536

// ---------------- scratch ----------------
__device__ float  g_x   [BS*DD];          // residual stream (fp32)
__device__ __half g_qkv16[3*BS*DD];       // q/k/v (B,H,S,DK) fp16
__device__ __half g_h16 [BS*DD];          // LN out / attn out (fp16 A operand)
__device__ __half g_in16[BS*INF_];
__device__ __half g_ff16[BS*FF_];
__device__ __half g_wi16[INF_*DD];        // transposed [N,K] fp16 weights
__device__ __half g_wqkv16[LL*NQKV*DD];   // concatenated [Wq;Wk;Wv]^T per layer
__device__ __half g_wo16[LL*DD*DD];
__device__ __half g_w116[LL*DD*FF_];
__device__ __half g_w216[LL*FF_*DD];
__device__ float  g_bqkv[LL*NQKV];
__device__ float  g_pe  [SS*DD];          // precomputed sinusoidal PE (2 MB)

// ---------------- mma.sync helpers ----------------
__device__ __forceinline__ void cp_async16(uint32_t dst, const void* src) {
    asm volatile("cp.async.ca.shared.global [%0], [%1], 16;" :: "r"(dst), "l"(src) : "memory");
}
__device__ __forceinline__ void cp_commit() {
    asm volatile("cp.async.commit_group;" ::: "memory");
}
template<int N>
__device__ __forceinline__ void cp_wait() {
    asm volatile("cp.async.wait_group %0;" :: "n"(N) : "memory");
}
__device__ __forceinline__ void ldmx4(uint32_t& r0, uint32_t& r1, uint32_t& r2, uint32_t& r3, uint32_t addr) {
    asm volatile("ldmatrix.sync.aligned.m8n8.x4.shared.b16 {%0,%1,%2,%3}, [%4];"
                 : "=r"(r0), "=r"(r1), "=r"(r2), "=r"(r3) : "r"(addr));
}
__device__ __forceinline__ void ldmx4t(uint32_t& r0, uint32_t& r1, uint32_t& r2, uint32_t& r3, uint32_t addr) {
    asm volatile("ldmatrix.sync.aligned.m8n8.x4.trans.shared.b16 {%0,%1,%2,%3}, [%4];"
                 : "=r"(r0), "=r"(r1), "=r"(r2), "=r"(r3) : "r"(addr));
}
__device__ __forceinline__ void mma16816(float* c, const uint32_t* a, const uint32_t* b) {
    asm volatile("mma.sync.aligned.m16n8k16.row.col.f32.f16.f16.f32 "
                 "{%0,%1,%2,%3}, {%4,%5,%6,%7}, {%8,%9}, {%0,%1,%2,%3};"
                 : "+f"(c[0]), "+f"(c[1]), "+f"(c[2]), "+f"(c[3])
                 : "r"(a[0]), "r"(a[1]), "r"(a[2]), "r"(a[3]), "r"(b[0]), "r"(b[1]));
}

// fast exp2 via FMA-pipe polynomial; valid for t <= 0
__device__ __forceinline__ float exp2p(float t) {
    t = fmaxf(t, -126.f);
    float z = t + 12582912.f;
    float f = t - (z - 12582912.f);
    float p = 0.00961804886f;
    p = fmaf(p, f, 0.0555041086f);
    p = fmaf(p, f, 0.2402265069f);
    p = fmaf(p, f, 0.6931471806f);
    p = fmaf(p, f, 1.0f);
    return __int_as_float(__float_as_int(p) + (__float_as_int(z) << 23));
}
__device__ __forceinline__ uint32_t f2h2(float a, float b) {
    __half2 h = __floats2half2_rn(a, b);
    return *(uint32_t*)&h;
}

// ================= fused prep kernel =================
#define PR_CONV_END 256
#define PR_WIN_END  (PR_CONV_END + 128)
#define PR_QKV_END  (PR_WIN_END + 1536)
#define PR_WO_END   (PR_QKV_END + 512)
#define PR_W1_END   (PR_WO_END + 2048)
#define PR_W2_END   (PR_W1_END + 2048)
#define PR_BIAS_END (PR_W2_END + 12)
#define PR_PE_END   (PR_BIAS_END + 1024)

__global__ void prep_kernel(const float* __restrict__ inputs, const float* __restrict__ W_in,
                            const float* __restrict__ Wq, const float* __restrict__ Wk,
                            const float* __restrict__ Wv, const float* __restrict__ Wo,
                            const float* __restrict__ W1, const float* __restrict__ W2,
                            const float* __restrict__ bq, const float* __restrict__ bk,
                            const float* __restrict__ bv,
                            __half* __restrict__ in16, __half* __restrict__ wi16,
                            __half* __restrict__ wqkv, __half* __restrict__ wo16,
                            __half* __restrict__ w116, __half* __restrict__ w216,
                            float* __restrict__ bqkv, float* __restrict__ pe)
{
    __shared__ float t[32][33];
    const int blk = blockIdx.x, tid = threadIdx.x;

    if (blk < PR_CONV_END) {
        const int base4 = blk * 2048 + tid;          // float4 index
#pragma unroll
        for (int j = 0; j < 8; j++) {
            float4 v = *(const float4*)(inputs + (size_t)(base4 + j * 256) * 4);
            uint32_t lo = f2h2(v.x, v.y), hi = f2h2(v.z, v.w);
            *(uint2*)(in16 + (size_t)(base4 + j * 256) * 4) = make_uint2(lo, hi);
        }
        return;
    }
    if (blk >= PR_BIAS_END) {
        const int p = (blk - PR_BIAS_END) * 256 + tid;
        const int s = p / (DD / 2), ce2 = p % (DD / 2);
        float div = __expf(-(float)(2 * ce2) * (9.210340371976184f / (float)DD));
        float sn, cs;
        __sincosf((float)s * div, &sn, &cs);
        *(float2*)(pe + (size_t)s * DD + 2 * ce2) = make_float2(sn, cs);
        return;
    }
    if (blk >= PR_W2_END) {
        const int idx = (blk - PR_W2_END) * 256 + tid;
        if (idx < LL * NQKV) {
            const int l = idx / NQKV, c = idx % NQKV;
            float v = (c < 512) ? bq[l * 512 + c]
                    : (c < 1024) ? bk[l * 512 + c - 512]
                                 : bv[l * 512 + c - 1024];
            bqkv[idx] = v;
        }
        return;
    }

    const float* src; __half* dst; int K, N, tile;
    if (blk < PR_WIN_END) {
        tile = blk - PR_CONV_END; K = INF_; N = DD; src = W_in; dst = wi16;
    } else if (blk < PR_QKV_END) {
        int r = blk - PR_WIN_END;
        int l = r / 768, r2 = r % 768, w = r2 >> 8;
        tile = r2 & 255; K = DD; N = DD;
        src = ((w == 0) ? Wq : (w == 1) ? Wk : Wv) + (size_t)l * DD * DD;
        dst = wqkv + (size_t)l * NQKV * DD + (size_t)w * DD * DD;
    } else if (blk < PR_WO_END) {
        int r = blk - PR_QKV_END;
        int l = r >> 8; tile = r & 255; K = DD; N = DD;
        src = Wo + (size_t)l * DD * DD; dst = wo16 + (size_t)l * DD * DD;
    } else if (blk < PR_W1_END) {
        int r = blk - PR_WO_END;
        int l = r >> 10; tile = r & 1023; K = DD; N = FF_;
        src = W1 + (size_t)l * DD * FF_; dst = w116 + (size_t)l * DD * FF_;
    } else {
        int r = blk - PR_W1_END;
        int l = r >> 10; tile = r & 1023; K = FF_; N = DD;
        src = W2 + (size_t)l * FF_ * DD; dst = w216 + (size_t)l * FF_ * DD;
    }

    const int tiles_x = N >> 5;
    const int k0 = (tile / tiles_x) << 5, n0 = (tile % tiles_x) << 5;
    const int x = tid & 31, y = tid >> 5;
#pragma unroll
    for (int i = 0; i < 32; i += 8) t[y + i][x] = src[(size_t)(k0 + y + i) * N + n0 + x];
    __syncthreads();
#pragma unroll
    for (int i = 0; i < 32; i += 8)
        dst[(size_t)(n0 + y + i) * K + k0 + x] = __float2half(t[x][y + i]);
}

// ===== HMMA fp16 GEMM: 128x128 CTA, 4 warps (warp 64x64), 3-stage, 2 CTAs/SM =====
#define BM 128
#define BN 128
#define LDH 40
#define GEMM_SMEM (3 * (BM + BN) * LDH * 2)   // 61440 B dynamic

// OUT_MODE: 0 = fp32 row-major; 2 = fp16 row-major; 3 = QKV scatter (B,H,S,DK) x3
template<int OUT_MODE, bool RELU, bool ADD_PE, bool HAS_RES>
__global__ __launch_bounds__(128, 2)
void gemm16(const __half* __restrict__ A, const __half* __restrict__ Bt,
            const float* __restrict__ bias, const float* __restrict__ resid,
            float* __restrict__ Cf, __half* __restrict__ C16, int K, int N, float os_q,
            const int* __restrict__ lengths)
{
    extern __shared__ __align__(16) __half sm16[];
    const uint32_t sA = (uint32_t)__cvta_generic_to_shared(sm16);
    const uint32_t sB = sA + 3 * BM * LDH * 2;

    const int tid  = threadIdx.x;
    const int lane = tid & 31, wid = tid >> 5;
    const int wr = wid >> 1, wc = wid & 1;          // 2 x 2 warps, warp tile 64x64
    const int r0 = blockIdx.y * BM, n0 = blockIdx.x * BN;

    // QKV: skip fully-masked K/V tiles (outputs never read by attention).
    if (OUT_MODE == 3) {
        if (n0 >= 512) {
            const int bI = r0 >> 10, s0 = r0 & (SS - 1);
            if (s0 >= lengths[bI]) return;
        }
    }

    float acc[4][8][4];
#pragma unroll
    for (int i = 0; i < 4; i++)
#pragma unroll
        for (int j = 0; j < 8; j++)
#pragma unroll
            for (int k = 0; k < 4; k++) acc[i][j][k] = 0.f;

    const int T = K >> 5;

#define LOADT(buf, k0)                                                        \
    do {                                                                      \
        _Pragma("unroll")                                                     \
        for (int i = 0; i < 4; i++) {                                         \
            int c_ = tid + i * 128;                                           \
            int row = c_ >> 2, cc = c_ & 3;                                   \
            uint32_t d = sA + ((buf) * BM * LDH + row * LDH + cc * 8) * 2;    \
            cp_async16(d, A + (size_t)(r0 + row) * K + (k0) + cc * 8);        \
        }                                                                     \
        _Pragma("unroll")                                                     \
        for (int i = 0; i < 4; i++) {                                         \
            int c_ = tid + i * 128;                                           \
            int row = c_ >> 2, cc = c_ & 3;                                   \
            uint32_t d = sB + ((buf) * BN * LDH + row * LDH + cc * 8) * 2;    \
            cp_async16(d, Bt + (size_t)(n0 + row) * K + (k0) + cc * 8);       \
        }                                                                     \
    } while (0)

    LOADT(0, 0);  cp_commit();
    LOADT(1, 32); cp_commit();

    const int lrow = lane & 15, lcol = (lane >> 4) * 8;
    const int bg = lane >> 3, br = lane & 7;
    const int brow = ((bg >> 1) * 8) + br, bcol = (bg & 1) * 8;

    for (int t = 0; t < T; t++) {
        if (t == T - 1) cp_wait<0>(); else cp_wait<1>();
        __syncthreads();

        if (t + 2 < T) { LOADT((t + 2) % 3, (t + 2) << 5); cp_commit(); }

        const int cur = t % 3;
#pragma unroll
        for (int ks = 0; ks < 2; ks++) {
            uint32_t af[4][4];
#pragma unroll
            for (int mt = 0; mt < 4; mt++) {
                uint32_t addr = sA + (cur * BM * LDH +
                    (wr * 64 + mt * 16 + lrow) * LDH + ks * 16 + lcol) * 2;
                ldmx4(af[mt][0], af[mt][1], af[mt][2], af[mt][3], addr);
            }
            uint32_t bf[8][2];
#pragma unroll
            for (int np = 0; np < 4; np++) {
                uint32_t addr = sB + (cur * BN * LDH +
                    (wc * 64 + np * 16 + brow) * LDH + ks * 16 + bcol) * 2;
                uint32_t q0, q1, q2, q3;
                ldmx4(q0, q1, q2, q3, addr);
                bf[np * 2][0] = q0; bf[np * 2][1] = q1;
                bf[np * 2 + 1][0] = q2; bf[np * 2 + 1][1] = q3;
            }
#pragma unroll
            for (int mt = 0; mt < 4; mt++)
#pragma unroll
                for (int nt = 0; nt < 8; nt++)
                    mma16816(acc[mt][nt], af[mt], bf[nt]);
        }
    }

    // ---------------- epilogue ----------------
    float* pe = nullptr;
    if (ADD_PE) { asm("cvta.global.u64 %0, %1;" : "=l"(pe) : "l"((void*)g_pe)); }

#pragma unroll
    for (int mt = 0; mt < 4; mt++) {
#pragma unroll
        for (int nt = 0; nt < 8; nt++) {
#pragma unroll
            for (int half_m = 0; half_m < 2; half_m++) {
                const int m   = r0 + wr * 64 + mt * 16 + (lane >> 2) + half_m * 8;
                const int col = n0 + wc * 64 + nt * 8 + 2 * (lane & 3);
                float v0 = acc[mt][nt][half_m * 2 + 0] + bias[col];
                float v1 = acc[mt][nt][half_m * 2 + 1] + bias[col + 1];
                if (RELU) { v0 = fmaxf(v0, 0.f); v1 = fmaxf(v1, 0.f); }
                const int s = m & (SS - 1);
                if (ADD_PE) {
                    float2 p2 = *(const float2*)(pe + (size_t)s * DD + col);
                    v0 += p2.x;
                    v1 += p2.y;
                }
                if (HAS_RES) {
                    v0 += resid[(size_t)m * N + col];
                    v1 += resid[(size_t)m * N + col + 1];
                }
                if (OUT_MODE == 0) {
                    *(float2*)(Cf + (size_t)m * N + col) = make_float2(v0, v1);
                } else if (OUT_MODE == 2) {
                    *(__half2*)(C16 + (size_t)m * N + col) = __floats2half2_rn(v0, v1);
                } else {   // QKV scatter
                    const int sec = col >> 9, cs = col & 511;
                    const float sc = (sec == 0) ? os_q : 1.f;
                    v0 *= sc; v1 *= sc;
                    const int bI = m >> 10;
                    const int hh = cs >> 6, dk = cs & (DK - 1);
                    __half* dst = C16 + (size_t)sec * (BS * DD) +
                                  (((size_t)(bI * HH + hh)) * SS + s) * DK + dk;
                    *(__half2*)dst = __floats2half2_rn(v0, v1);
                }
            }
        }
    }
#undef LOADT
}

// ================= LayerNorm (2 rows / 256-thread block, float4) =================
__device__ __forceinline__ float half_block_sum(float v, int half, int w4)
{
    __shared__ float red[2][4];
    const int lane = threadIdx.x & 31;
#pragma unroll
    for (int o = 16; o; o >>= 1) v += __shfl_xor_sync(0xffffffffu, v, o);
    if (lane == 0) red[half][w4] = v;
    __syncthreads();
    float s = red[half][0] + red[half][1] + red[half][2] + red[half][3];
    __syncthreads();
    return s;
}

template<bool H16>
__global__ void ln_kernel(const float* __restrict__ x, const float* __restrict__ g,
                          const float* __restrict__ be, float* __restrict__ yf,
                          __half* __restrict__ yh)
{
    const int half = threadIdx.x >> 7;
    const int t    = threadIdx.x & 127;
    const int w4   = (threadIdx.x >> 5) & 3;
    const int row  = blockIdx.x * 2 + half;

    const float4 v = *(const float4*)(x + (size_t)row * DD + t * 4);
    float mean = half_block_sum(v.x + v.y + v.z + v.w, half, w4) * (1.0f / DD);
    float d0 = v.x - mean, d1 = v.y - mean, d2 = v.z - mean, d3 = v.w - mean;
    float var = half_block_sum(d0 * d0 + d1 * d1 + d2 * d2 + d3 * d3, half, w4) * (1.0f / DD);
    float rstd = rsqrtf(var + EPS);

    const float4 gv = *(const float4*)(g  + t * 4);
    const float4 bv = *(const float4*)(be + t * 4);
    float o0 = d0 * rstd * gv.x + bv.x;
    float o1 = d1 * rstd * gv.y + bv.y;
    float o2 = d2 * rstd * gv.z + bv.z;
    float o3 = d3 * rstd * gv.w + bv.w;

    if (H16) {
        uint32_t lo = f2h2(o0, o1), hi = f2h2(o2, o3);
        *(uint2*)(yh + (size_t)row * DD + t * 4) = make_uint2(lo, hi);
    } else {
        *(float4*)(yf + (size_t)row * DD + t * 4) = make_float4(o0, o1, o2, o3);
    }
}

// ================= fused HMMA flash attention =================
#define PITCH 72
#define ATT_SMEM (512 + 128*PITCH*2 + 2*64*PITCH*2 + 2*64*PITCH*2)   // 55808

__global__ __launch_bounds__(256, 2)
void attn_mma(const __half* __restrict__ Qg_, const __half* __restrict__ Kg_,
              const __half* __restrict__ Vg_, const float* __restrict__ rb,
              const int* __restrict__ lengths, __half* __restrict__ out)
{
    extern __shared__ __align__(16) char smem_raw[];
    float*  bias_s = (float*)smem_raw;
    __half* Qs = (__half*)(smem_raw + 512);
    __half* Ks = (__half*)(smem_raw + 512 + 18432);
    __half* Vs = (__half*)(smem_raw + 512 + 36864);

    const int tid = threadIdx.x, lane = tid & 31, wr = tid >> 5;
    const int blk = blockIdx.x;
    const int qt = blk & 7, bh = blk >> 3;
    const int h = bh & (HH - 1), b = bh >> 3;
    const int q0 = qt * 128;
    const int len = lengths[b];
    const int nc = (len + 63) >> 6;

    if (tid < 127) bias_s[tid] = rb[h * 127 + tid] * 1.44269504f;

    const __half* Qg = Qg_ + ((size_t)bh * SS + q0) * DK;
    const __half* Kg = Kg_ + (size_t)bh * SS * DK;
    const __half* Vg = Vg_ + (size_t)bh * SS * DK;

#pragma unroll
    for (int i = 0; i < 4; i++) {
        int idx = tid + i * 256; int row = idx >> 3, c = idx & 7;
        cp_async16((uint32_t)__cvta_generic_to_shared(Qs + row * PITCH + c * 8),
                   Qg + (size_t)row * DK + c * 8);
    }
#pragma unroll
    for (int i = 0; i < 2; i++) {
        int idx = tid + i * 256; int row = idx >> 3, c = idx & 7;
        cp_async16((uint32_t)__cvta_generic_to_shared(Ks + row * PITCH + c * 8),
                   Kg + (size_t)row * DK + c * 8);
        cp_async16((uint32_t)__cvta_generic_to_shared(Vs + row * PITCH + c * 8),
                   Vg + (size_t)row * DK + c * 8);
    }
    cp_commit();

    float m0 = -1e30f, m1 = -1e30f, l0 = 0.f, l1 = 0.f;
    float oacc[8][4];
#pragma unroll
    for (int i = 0; i < 8; i++)
#pragma unroll
        for (int j = 0; j < 4; j++) oacc[i][j] = 0.f;
    uint32_t aQ[4][4];

    const int r = lane >> 2;
    const int qg0 = q0 + wr * 16 + r;
    const int qg1 = qg0 + 8;

    for (int cc = 0; cc < nc; cc++) {
        const int buf = cc & 1;
        if (cc + 1 < nc) {
            const int nb = buf ^ 1;
#pragma unroll
            for (int i = 0; i < 2; i++) {
                int idx = tid + i * 256; int row = idx >> 3, c = idx & 7;
                cp_async16((uint32_t)__cvta_generic_to_shared(Ks + nb * 64 * PITCH + row * PITCH + c * 8),
                           Kg + (size_t)((cc + 1) * 64 + row) * DK + c * 8);
                cp_async16((uint32_t)__cvta_generic_to_shared(Vs + nb * 64 * PITCH + row * PITCH + c * 8),
                           Vg + (size_t)((cc + 1) * 64 + row) * DK + c * 8);
            }
            cp_commit();
            cp_wait<1>();
        } else {
            cp_wait<0>();
        }
        __syncthreads();

        if (cc == 0) {
#pragma unroll
            for (int ks = 0; ks < 4; ks++) {
                const __half* p = Qs + (wr * 16 + ((lane >> 3) & 1) * 8 + (lane & 7)) * PITCH
                                  + ks * 16 + (lane >> 4) * 8;
                ldmx4(aQ[ks][0], aQ[ks][1], aQ[ks][2], aQ[ks][3],
                      (uint32_t)__cvta_generic_to_shared(p));
            }
        }

        const __half* kb = Ks + buf * 64 * PITCH;
        float sacc[8][4];
#pragma unroll
        for (int i = 0; i < 8; i++)
#pragma unroll
            for (int j = 0; j < 4; j++) sacc[i][j] = 0.f;
        const int g = lane >> 3, gi = lane & 7;
#pragma unroll
        for (int ks = 0; ks < 4; ks++) {
            uint32_t bK[8][2];
#pragma unroll
            for (int np = 0; np < 4; np++) {
                const __half* p = kb + (np * 16 + ((g >> 1) << 3) + gi) * PITCH
                                  + ks * 16 + ((g & 1) << 3);
                uint32_t t0, t1, t2, t3;
                ldmx4(t0, t1, t2, t3, (uint32_t)__cvta_generic_to_shared(p));
                bK[2 * np][0] = t0; bK[2 * np][1] = t1;
                bK[2 * np + 1][0] = t2; bK[2 * np + 1][1] = t3;
            }
#pragma unroll
            for (int nt = 0; nt < 8; nt++) mma16816(sacc[nt], aQ[ks], bK[nt]);
        }

        // ----- bias + mask fixup: full chunks skip the mask entirely -----
        const int kb0 = cc * 64;
        const bool full = (kb0 + 64 <= len);   // uniform across CTA
        float mc0 = -1e30f, mc1 = -1e30f;
        if (full) {
#pragma unroll
            for (int nt = 0; nt < 8; nt++) {
                const int k0i = kb0 + nt * 8 + 2 * (lane & 3);
#pragma unroll
                for (int e = 0; e < 4; e++) {
                    const int kk = k0i + (e & 1);
                    const int qq = (e < 2) ? qg0 : qg1;
                    int rel = min(63, max(-63, qq - kk)) + 63;
                    float val = sacc[nt][e] + bias_s[rel];
                    sacc[nt][e] = val;
                    if (e < 2) mc0 = fmaxf(mc0, val); else mc1 = fmaxf(mc1, val);
                }
            }
        } else {
#pragma unroll
            for (int nt = 0; nt < 8; nt++) {
                const int k0i = kb0 + nt * 8 + 2 * (lane & 3);
#pragma unroll
                for (int e = 0; e < 4; e++) {
                    const int kk = k0i + (e & 1);
                    const int qq = (e < 2) ? qg0 : qg1;
                    int rel = min(63, max(-63, qq - kk)) + 63;
                    float val = sacc[nt][e] + bias_s[rel];
                    if (kk >= len) val = -1e30f;
                    sacc[nt][e] = val;
                    if (e < 2) mc0 = fmaxf(mc0, val); else mc1 = fmaxf(mc1, val);
                }
            }
        }
        mc0 = fmaxf(mc0, __shfl_xor_sync(0xffffffffu, mc0, 1));
        mc0 = fmaxf(mc0, __shfl_xor_sync(0xffffffffu, mc0, 2));
        mc1 = fmaxf(mc1, __shfl_xor_sync(0xffffffffu, mc1, 1));
        mc1 = fmaxf(mc1, __shfl_xor_sync(0xffffffffu, mc1, 2));
        const float mn0 = fmaxf(m0, mc0), mn1 = fmaxf(m1, mc1);
        const float al0 = exp2p(m0 - mn0), al1 = exp2p(m1 - mn1);
        m0 = mn0; m1 = mn1;

        float ps0 = 0.f, ps1 = 0.f;
        uint32_t aP[4][4];
#pragma unroll
        for (int nt = 0; nt < 8; nt++) {
            float p0 = exp2p(sacc[nt][0] - mn0);
            float p1 = exp2p(sacc[nt][1] - mn0);
            float p2 = exp2p(sacc[nt][2] - mn1);
            float p3 = exp2p(sacc[nt][3] - mn1);
            ps0 += p0 + p1; ps1 += p2 + p3;
            uint32_t lo = f2h2(p0, p1), hi = f2h2(p2, p3);
            if ((nt & 1) == 0) { aP[nt >> 1][0] = lo; aP[nt >> 1][1] = hi; }
            else               { aP[nt >> 1][2] = lo; aP[nt >> 1][3] = hi; }
        }
        ps0 += __shfl_xor_sync(0xffffffffu, ps0, 1);
        ps0 += __shfl_xor_sync(0xffffffffu, ps0, 2);
        ps1 += __shfl_xor_sync(0xffffffffu, ps1, 1);
        ps1 += __shfl_xor_sync(0xffffffffu, ps1, 2);
        l0 = l0 * al0 + ps0;
        l1 = l1 * al1 + ps1;
#pragma unroll
        for (int nt = 0; nt < 8; nt++) {
            oacc[nt][0] *= al0; oacc[nt][1] *= al0;
            oacc[nt][2] *= al1; oacc[nt][3] *= al1;
        }

        const __half* vb = Vs + buf * 64 * PITCH;
#pragma unroll
        for (int kc = 0; kc < 4; kc++) {
            uint32_t bV[8][2];
#pragma unroll
            for (int np = 0; np < 4; np++) {
                const __half* p = vb + (kc * 16 + ((g & 1) << 3) + gi) * PITCH
                                  + np * 16 + ((g >> 1) << 3);
                uint32_t t0, t1, t2, t3;
                ldmx4t(t0, t1, t2, t3, (uint32_t)__cvta_generic_to_shared(p));
                bV[2 * np][0] = t0; bV[2 * np][1] = t1;
                bV[2 * np + 1][0] = t2; bV[2 * np + 1][1] = t3;
            }
#pragma unroll
            for (int nt = 0; nt < 8; nt++) mma16816(oacc[nt], aP[kc], bV[nt]);
        }
        __syncthreads();
    }

    const float inv0 = 1.f / l0, inv1 = 1.f / l1;
    __half* o0p = out + ((size_t)(b * SS + qg0)) * DD + h * DK + 2 * (lane & 3);
    __half* o1p = out + ((size_t)(b * SS + qg1)) * DD + h * DK + 2 * (lane & 3);
#pragma unroll
    for (int nt = 0; nt < 8; nt++) {
        *(__half2*)(o0p + nt * 8) = __floats2half2_rn(oacc[nt][0] * inv0, oacc[nt][1] * inv0);
        *(__half2*)(o1p + nt * 8) = __floats2half2_rn(oacc[nt][2] * inv1, oacc[nt][3] * inv1);
    }
}

// ================= host orchestration =================
#define G_PROJ gemm16<0, false, true,  false>
#define G_RES  gemm16<0, false, false, true >
#define G_QKV  gemm16<3, false, false, false>
#define G_FF1  gemm16<2, true,  false, false>

extern "C" void kernel_launch(void* const* d_in, const int* in_sizes, int n_in,
                              void* d_out, int out_size)
{
    const float* inputs  = (const float*)d_in[0];
    const int*   lengths = (const int*)  d_in[1];
    const float* W_in    = (const float*)d_in[2];
    const float* b_in    = (const float*)d_in[3];
    const float* Wq      = (const float*)d_in[4];
    const float* bq      = (const float*)d_in[5];
    const float* Wk      = (const float*)d_in[6];
    const float* bk      = (const float*)d_in[7];
    const float* Wv      = (const float*)d_in[8];
    const float* bv      = (const float*)d_in[9];
    const float* Wo      = (const float*)d_in[10];
    const float* bo      = (const float*)d_in[11];
    const float* rel_b   = (const float*)d_in[12];
    const float* W1      = (const float*)d_in[13];
    const float* b1      = (const float*)d_in[14];
    const float* W2      = (const float*)d_in[15];
    const float* b2      = (const float*)d_in[16];
    const float* g1      = (const float*)d_in[17];
    const float* be1     = (const float*)d_in[18];
    const float* g2      = (const float*)d_in[19];
    const float* be2     = (const float*)d_in[20];
    const float* gf      = (const float*)d_in[21];
    const float* bef     = (const float*)d_in[22];

    float *x, *bqkv, *pe;
    __half *qkv16, *h16, *in16, *ff16, *wi16, *wqkv16, *wo16, *w116, *w216;
    cudaGetSymbolAddress((void**)&x,      g_x);
    cudaGetSymbolAddress((void**)&qkv16,  g_qkv16);
    cudaGetSymbolAddress((void**)&h16,    g_h16);
    cudaGetSymbolAddress((void**)&in16,   g_in16);
    cudaGetSymbolAddress((void**)&ff16,   g_ff16);
    cudaGetSymbolAddress((void**)&wi16,   g_wi16);
    cudaGetSymbolAddress((void**)&wqkv16, g_wqkv16);
    cudaGetSymbolAddress((void**)&wo16,   g_wo16);
    cudaGetSymbolAddress((void**)&w116,   g_w116);
    cudaGetSymbolAddress((void**)&w216,   g_w216);
    cudaGetSymbolAddress((void**)&bqkv,   g_bqkv);
    cudaGetSymbolAddress((void**)&pe,     g_pe);

    cudaFuncSetAttribute(attn_mma, cudaFuncAttributeMaxDynamicSharedMemorySize, ATT_SMEM);
    cudaFuncSetAttribute(G_PROJ, cudaFuncAttributeMaxDynamicSharedMemorySize, GEMM_SMEM);
    cudaFuncSetAttribute(G_RES,  cudaFuncAttributeMaxDynamicSharedMemorySize, GEMM_SMEM);
    cudaFuncSetAttribute(G_QKV,  cudaFuncAttributeMaxDynamicSharedMemorySize, GEMM_SMEM);
    cudaFuncSetAttribute(G_FF1,  cudaFuncAttributeMaxDynamicSharedMemorySize, GEMM_SMEM);

    prep_kernel<<<PR_PE_END, 256>>>(inputs, W_in, Wq, Wk, Wv, Wo, W1, W2, bq, bk, bv,
                                    in16, wi16, wqkv16, wo16, w116, w216, bqkv, pe);

    const dim3 gD(DD / BN,   BS / BM);    // (4, 64)
    const dim3 gQ(NQKV / BN, BS / BM);    // (12, 64)
    const dim3 gF1(FF_ / BN, BS / BM);    // (16, 64)
    const float QSCALE = 0.125f * 1.44269504f;

    __half* q16 = qkv16;
    __half* k16 = qkv16 + (size_t)BS * DD;
    __half* v16 = qkv16 + 2 * (size_t)BS * DD;

    G_PROJ<<<gD, 128, GEMM_SMEM>>>(in16, wi16, b_in, nullptr, x, nullptr, INF_, DD, 1.0f, nullptr);

    for (int l = 0; l < LL; l++) {
        const __half* wqkv = wqkv16 + (size_t)l * NQKV * DD;
        const __half* wo = wo16 + (size_t)l * DD * DD;
        const __half* w1 = w116 + (size_t)l * DD * FF_;
        const __half* w2 = w216 + (size_t)l * FF_ * DD;

        ln_kernel<true><<<BS / 2, 256>>>(x, g1 + l * DD, be1 + l * DD, nullptr, h16);
        G_QKV<<<gQ, 128, GEMM_SMEM>>>(h16, wqkv, bqkv + l * NQKV, nullptr,
                                      nullptr, qkv16, DD, NQKV, QSCALE, lengths);

        attn_mma<<<BB * HH * (SS / 128), 256, ATT_SMEM>>>(q16, k16, v16,
                                                          rel_b + (size_t)l * HH * (2 * MM - 1),
                                                          lengths, h16);

        G_RES<<<gD, 128, GEMM_SMEM>>>(h16, wo, bo + l * DD, x, x, nullptr, DD, DD, 1.0f, nullptr);

        ln_kernel<true><<<BS / 2, 256>>>(x, g2 + l * DD, be2 + l * DD, nullptr, h16);
        G_FF1<<<gF1, 128, GEMM_SMEM>>>(h16, w1, b1 + l * FF_, nullptr,
                                       nullptr, ff16, DD, FF_, 1.0f, nullptr);
        G_RES<<<gD, 128, GEMM_SMEM>>>(ff16, w2, b2 + l * DD, x, x, nullptr, FF_, DD, 1.0f, nullptr);
    }

    ln_kernel<false><<<BS / 2, 256>>>(x, gf, bef, (float*)d_out, nullptr);
}

// round 17
// speedup vs baseline: 1.0983x; 1.0088x over previous
#include <cuda_runtime.h>
#include <cuda_fp16.h>
#include <math.h>
#include <stdint.h>

// ---------------- problem constants ----------------
#define BB   8
#define SS   1024
#define INF_ 256
#define DD   512
#define HH   8
#define LL   2
#define MM   64
#define DK   64
#define FF_  2048
#define BS   (BB*SS)          // 8192 rows
#define EPS  1e-5f
#define NQKV 1536

// ---------------- scratch ----------------
__device__ float  g_x   [BS*DD];          // residual stream (fp32)
__device__ __half g_qkv16[3*BS*DD];       // q/k/v (B,H,S,DK) fp16
__device__ __half g_h16 [BS*DD];          // LN out / attn out (fp16 A operand)
__device__ __half g_in16[BS*INF_];
__device__ __half g_ff16[BS*FF_];
__device__ __half g_wi16[INF_*DD];        // transposed [N,K] fp16 weights
__device__ __half g_wqkv16[LL*NQKV*DD];   // concatenated [Wq;Wk;Wv]^T per layer
__device__ __half g_wo16[LL*DD*DD];
__device__ __half g_w116[LL*DD*FF_];
__device__ __half g_w216[LL*FF_*DD];
__device__ float  g_bqkv[LL*NQKV];
__device__ float  g_pe  [SS*DD];          // precomputed sinusoidal PE (2 MB)

// ---------------- mma.sync helpers ----------------
__device__ __forceinline__ void cp_async16(uint32_t dst, const void* src) {
    asm volatile("cp.async.ca.shared.global [%0], [%1], 16;" :: "r"(dst), "l"(src) : "memory");
}
__device__ __forceinline__ void cp_commit() {
    asm volatile("cp.async.commit_group;" ::: "memory");
}
template<int N>
__device__ __forceinline__ void cp_wait() {
    asm volatile("cp.async.wait_group %0;" :: "n"(N) : "memory");
}
__device__ __forceinline__ void ldmx4(uint32_t& r0, uint32_t& r1, uint32_t& r2, uint32_t& r3, uint32_t addr) {
    asm volatile("ldmatrix.sync.aligned.m8n8.x4.shared.b16 {%0,%1,%2,%3}, [%4];"
                 : "=r"(r0), "=r"(r1), "=r"(r2), "=r"(r3) : "r"(addr));
}
__device__ __forceinline__ void ldmx4t(uint32_t& r0, uint32_t& r1, uint32_t& r2, uint32_t& r3, uint32_t addr) {
    asm volatile("ldmatrix.sync.aligned.m8n8.x4.trans.shared.b16 {%0,%1,%2,%3}, [%4];"
                 : "=r"(r0), "=r"(r1), "=r"(r2), "=r"(r3) : "r"(addr));
}
__device__ __forceinline__ void mma16816(float* c, const uint32_t* a, const uint32_t* b) {
    asm volatile("mma.sync.aligned.m16n8k16.row.col.f32.f16.f16.f32 "
                 "{%0,%1,%2,%3}, {%4,%5,%6,%7}, {%8,%9}, {%0,%1,%2,%3};"
                 : "+f"(c[0]), "+f"(c[1]), "+f"(c[2]), "+f"(c[3])
                 : "r"(a[0]), "r"(a[1]), "r"(a[2]), "r"(a[3]), "r"(b[0]), "r"(b[1]));
}

// fast exp2 via FMA-pipe polynomial; valid for t <= 0
__device__ __forceinline__ float exp2p(float t) {
    t = fmaxf(t, -126.f);
    float z = t + 12582912.f;
    float f = t - (z - 12582912.f);
    float p = 0.00961804886f;
    p = fmaf(p, f, 0.0555041086f);
    p = fmaf(p, f, 0.2402265069f);
    p = fmaf(p, f, 0.6931471806f);
    p = fmaf(p, f, 1.0f);
    return __int_as_float(__float_as_int(p) + (__float_as_int(z) << 23));
}
__device__ __forceinline__ uint32_t f2h2(float a, float b) {
    __half2 h = __floats2half2_rn(a, b);
    return *(uint32_t*)&h;
}

// ================= fused prep kernel =================
#define PR_CONV_END 256
#define PR_WIN_END  (PR_CONV_END + 128)
#define PR_QKV_END  (PR_WIN_END + 1536)
#define PR_WO_END   (PR_QKV_END + 512)
#define PR_W1_END   (PR_WO_END + 2048)
#define PR_W2_END   (PR_W1_END + 2048)
#define PR_BIAS_END (PR_W2_END + 12)
#define PR_PE_END   (PR_BIAS_END + 1024)

__global__ void prep_kernel(const float* __restrict__ inputs, const float* __restrict__ W_in,
                            const float* __restrict__ Wq, const float* __restrict__ Wk,
                            const float* __restrict__ Wv, const float* __restrict__ Wo,
                            const float* __restrict__ W1, const float* __restrict__ W2,
                            const float* __restrict__ bq, const float* __restrict__ bk,
                            const float* __restrict__ bv,
                            __half* __restrict__ in16, __half* __restrict__ wi16,
                            __half* __restrict__ wqkv, __half* __restrict__ wo16,
                            __half* __restrict__ w116, __half* __restrict__ w216,
                            float* __restrict__ bqkv, float* __restrict__ pe)
{
    __shared__ float t[32][33];
    const int blk = blockIdx.x, tid = threadIdx.x;

    if (blk < PR_CONV_END) {
        const int base4 = blk * 2048 + tid;          // float4 index
#pragma unroll
        for (int j = 0; j < 8; j++) {
            float4 v = *(const float4*)(inputs + (size_t)(base4 + j * 256) * 4);
            uint32_t lo = f2h2(v.x, v.y), hi = f2h2(v.z, v.w);
            *(uint2*)(in16 + (size_t)(base4 + j * 256) * 4) = make_uint2(lo, hi);
        }
        return;
    }
    if (blk >= PR_BIAS_END) {
        const int p = (blk - PR_BIAS_END) * 256 + tid;
        const int s = p / (DD / 2), ce2 = p % (DD / 2);
        float div = __expf(-(float)(2 * ce2) * (9.210340371976184f / (float)DD));
        float sn, cs;
        __sincosf((float)s * div, &sn, &cs);
        *(float2*)(pe + (size_t)s * DD + 2 * ce2) = make_float2(sn, cs);
        return;
    }
    if (blk >= PR_W2_END) {
        const int idx = (blk - PR_W2_END) * 256 + tid;
        if (idx < LL * NQKV) {
            const int l = idx / NQKV, c = idx % NQKV;
            float v = (c < 512) ? bq[l * 512 + c]
                    : (c < 1024) ? bk[l * 512 + c - 512]
                                 : bv[l * 512 + c - 1024];
            bqkv[idx] = v;
        }
        return;
    }

    const float* src; __half* dst; int K, N, tile;
    if (blk < PR_WIN_END) {
        tile = blk - PR_CONV_END; K = INF_; N = DD; src = W_in; dst = wi16;
    } else if (blk < PR_QKV_END) {
        int r = blk - PR_WIN_END;
        int l = r / 768, r2 = r % 768, w = r2 >> 8;
        tile = r2 & 255; K = DD; N = DD;
        src = ((w == 0) ? Wq : (w == 1) ? Wk : Wv) + (size_t)l * DD * DD;
        dst = wqkv + (size_t)l * NQKV * DD + (size_t)w * DD * DD;
    } else if (blk < PR_WO_END) {
        int r = blk - PR_QKV_END;
        int l = r >> 8; tile = r & 255; K = DD; N = DD;
        src = Wo + (size_t)l * DD * DD; dst = wo16 + (size_t)l * DD * DD;
    } else if (blk < PR_W1_END) {
        int r = blk - PR_WO_END;
        int l = r >> 10; tile = r & 1023; K = DD; N = FF_;
        src = W1 + (size_t)l * DD * FF_; dst = w116 + (size_t)l * DD * FF_;
    } else {
        int r = blk - PR_W1_END;
        int l = r >> 10; tile = r & 1023; K = FF_; N = DD;
        src = W2 + (size_t)l * FF_ * DD; dst = w216 + (size_t)l * FF_ * DD;
    }

    const int tiles_x = N >> 5;
    const int k0 = (tile / tiles_x) << 5, n0 = (tile % tiles_x) << 5;
    const int x = tid & 31, y = tid >> 5;
#pragma unroll
    for (int i = 0; i < 32; i += 8) t[y + i][x] = src[(size_t)(k0 + y + i) * N + n0 + x];
    __syncthreads();
#pragma unroll
    for (int i = 0; i < 32; i += 8)
        dst[(size_t)(n0 + y + i) * K + k0 + x] = __float2half(t[x][y + i]);
}

// ===== HMMA fp16 GEMM: 128x128 CTA, 4 warps (warp 64x64), 3-stage, 2 CTAs/SM =====
#define BM 128
#define BN 128
#define LDH 40
#define GEMM_SMEM (3 * (BM + BN) * LDH * 2)   // 61440 B dynamic

// OUT_MODE: 0 = fp32 row-major; 2 = fp16 row-major; 3 = QKV scatter (B,H,S,DK) x3
template<int OUT_MODE, bool RELU, bool ADD_PE, bool HAS_RES>
__global__ __launch_bounds__(128, 2)
void gemm16(const __half* __restrict__ A, const __half* __restrict__ Bt,
            const float* __restrict__ bias, const float* __restrict__ resid,
            float* __restrict__ Cf, __half* __restrict__ C16, int K, int N, float os_q,
            const int* __restrict__ lengths)
{
    extern __shared__ __align__(16) __half sm16[];
    const uint32_t sA = (uint32_t)__cvta_generic_to_shared(sm16);
    const uint32_t sB = sA + 3 * BM * LDH * 2;

    const int tid  = threadIdx.x;
    const int lane = tid & 31, wid = tid >> 5;
    const int wr = wid >> 1, wc = wid & 1;          // 2 x 2 warps, warp tile 64x64
    const int r0 = blockIdx.y * BM, n0 = blockIdx.x * BN;

    // QKV: skip fully-masked K/V tiles (outputs never read by attention).
    if (OUT_MODE == 3) {
        if (n0 >= 512) {
            const int bI = r0 >> 10, s0 = r0 & (SS - 1);
            if (s0 >= lengths[bI]) return;
        }
    }

    float acc[4][8][4];
#pragma unroll
    for (int i = 0; i < 4; i++)
#pragma unroll
        for (int j = 0; j < 8; j++)
#pragma unroll
            for (int k = 0; k < 4; k++) acc[i][j][k] = 0.f;

    const int T = K >> 5;

#define LOADT(buf, k0)                                                        \
    do {                                                                      \
        _Pragma("unroll")                                                     \
        for (int i = 0; i < 4; i++) {                                         \
            int c_ = tid + i * 128;                                           \
            int row = c_ >> 2, cc = c_ & 3;                                   \
            uint32_t d = sA + ((buf) * BM * LDH + row * LDH + cc * 8) * 2;    \
            cp_async16(d, A + (size_t)(r0 + row) * K + (k0) + cc * 8);        \
        }                                                                     \
        _Pragma("unroll")                                                     \
        for (int i = 0; i < 4; i++) {                                         \
            int c_ = tid + i * 128;                                           \
            int row = c_ >> 2, cc = c_ & 3;                                   \
            uint32_t d = sB + ((buf) * BN * LDH + row * LDH + cc * 8) * 2;    \
            cp_async16(d, Bt + (size_t)(n0 + row) * K + (k0) + cc * 8);       \
        }                                                                     \
    } while (0)

    LOADT(0, 0);  cp_commit();
    LOADT(1, 32); cp_commit();

    const int lrow = lane & 15, lcol = (lane >> 4) * 8;
    const int bg = lane >> 3, br = lane & 7;
    const int brow = ((bg >> 1) * 8) + br, bcol = (bg & 1) * 8;

    for (int t = 0; t < T; t++) {
        if (t == T - 1) cp_wait<0>(); else cp_wait<1>();
        __syncthreads();

        if (t + 2 < T) { LOADT((t + 2) % 3, (t + 2) << 5); cp_commit(); }

        const int cur = t % 3;
#pragma unroll
        for (int ks = 0; ks < 2; ks++) {
            uint32_t af[4][4];
#pragma unroll
            for (int mt = 0; mt < 4; mt++) {
                uint32_t addr = sA + (cur * BM * LDH +
                    (wr * 64 + mt * 16 + lrow) * LDH + ks * 16 + lcol) * 2;
                ldmx4(af[mt][0], af[mt][1], af[mt][2], af[mt][3], addr);
            }
            uint32_t bf[8][2];
#pragma unroll
            for (int np = 0; np < 4; np++) {
                uint32_t addr = sB + (cur * BN * LDH +
                    (wc * 64 + np * 16 + brow) * LDH + ks * 16 + bcol) * 2;
                uint32_t q0, q1, q2, q3;
                ldmx4(q0, q1, q2, q3, addr);
                bf[np * 2][0] = q0; bf[np * 2][1] = q1;
                bf[np * 2 + 1][0] = q2; bf[np * 2 + 1][1] = q3;
            }
#pragma unroll
            for (int mt = 0; mt < 4; mt++)
#pragma unroll
                for (int nt = 0; nt < 8; nt++)
                    mma16816(acc[mt][nt], af[mt], bf[nt]);
        }
    }

    // ---------------- epilogue ----------------
    float* pe = nullptr;
    if (ADD_PE) { asm("cvta.global.u64 %0, %1;" : "=l"(pe) : "l"((void*)g_pe)); }

#pragma unroll
    for (int mt = 0; mt < 4; mt++) {
#pragma unroll
        for (int nt = 0; nt < 8; nt++) {
#pragma unroll
            for (int half_m = 0; half_m < 2; half_m++) {
                const int m   = r0 + wr * 64 + mt * 16 + (lane >> 2) + half_m * 8;
                const int col = n0 + wc * 64 + nt * 8 + 2 * (lane & 3);
                float v0 = acc[mt][nt][half_m * 2 + 0] + bias[col];
                float v1 = acc[mt][nt][half_m * 2 + 1] + bias[col + 1];
                if (RELU) { v0 = fmaxf(v0, 0.f); v1 = fmaxf(v1, 0.f); }
                const int s = m & (SS - 1);
                if (ADD_PE) {
                    float2 p2 = *(const float2*)(pe + (size_t)s * DD + col);
                    v0 += p2.x;
                    v1 += p2.y;
                }
                if (HAS_RES) {
                    v0 += resid[(size_t)m * N + col];
                    v1 += resid[(size_t)m * N + col + 1];
                }
                if (OUT_MODE == 0) {
                    *(float2*)(Cf + (size_t)m * N + col) = make_float2(v0, v1);
                } else if (OUT_MODE == 2) {
                    *(__half2*)(C16 + (size_t)m * N + col) = __floats2half2_rn(v0, v1);
                } else {   // QKV scatter
                    const int sec = col >> 9, cs = col & 511;
                    const float sc = (sec == 0) ? os_q : 1.f;
                    v0 *= sc; v1 *= sc;
                    const int bI = m >> 10;
                    const int hh = cs >> 6, dk = cs & (DK - 1);
                    __half* dst = C16 + (size_t)sec * (BS * DD) +
                                  (((size_t)(bI * HH + hh)) * SS + s) * DK + dk;
                    *(__half2*)dst = __floats2half2_rn(v0, v1);
                }
            }
        }
    }
#undef LOADT
}

// ================= LayerNorm: warp-per-row, no barriers =================
template<bool H16>
__global__ void ln_kernel(const float* __restrict__ x, const float* __restrict__ g,
                          const float* __restrict__ be, float* __restrict__ yf,
                          __half* __restrict__ yh)
{
    const int warp = threadIdx.x >> 5, lane = threadIdx.x & 31;
    const int row  = blockIdx.x * 8 + warp;
    const float* xr = x + (size_t)row * DD;

    float4 v[4];
    float s = 0.f;
#pragma unroll
    for (int i = 0; i < 4; i++) {
        v[i] = *(const float4*)(xr + lane * 4 + i * 128);
        s += (v[i].x + v[i].y) + (v[i].z + v[i].w);
    }
#pragma unroll
    for (int o = 16; o; o >>= 1) s += __shfl_xor_sync(0xffffffffu, s, o);
    const float mean = s * (1.0f / DD);

    float var = 0.f;
#pragma unroll
    for (int i = 0; i < 4; i++) {
        v[i].x -= mean; v[i].y -= mean; v[i].z -= mean; v[i].w -= mean;
        var += (v[i].x * v[i].x + v[i].y * v[i].y) + (v[i].z * v[i].z + v[i].w * v[i].w);
    }
#pragma unroll
    for (int o = 16; o; o >>= 1) var += __shfl_xor_sync(0xffffffffu, var, o);
    const float rstd = rsqrtf(var * (1.0f / DD) + EPS);

#pragma unroll
    for (int i = 0; i < 4; i++) {
        const int c = lane * 4 + i * 128;
        const float4 gv = *(const float4*)(g  + c);
        const float4 bv = *(const float4*)(be + c);
        float o0 = v[i].x * rstd * gv.x + bv.x;
        float o1 = v[i].y * rstd * gv.y + bv.y;
        float o2 = v[i].z * rstd * gv.z + bv.z;
        float o3 = v[i].w * rstd * gv.w + bv.w;
        if (H16) {
            *(uint2*)(yh + (size_t)row * DD + c) = make_uint2(f2h2(o0, o1), f2h2(o2, o3));
        } else {
            *(float4*)(yf + (size_t)row * DD + c) = make_float4(o0, o1, o2, o3);
        }
    }
}

// ================= fused HMMA flash attention =================
#define PITCH 72
#define ATT_SMEM (512 + 128*PITCH*2 + 2*64*PITCH*2 + 2*64*PITCH*2)   // 55808

__global__ __launch_bounds__(256, 2)
void attn_mma(const __half* __restrict__ Qg_, const __half* __restrict__ Kg_,
              const __half* __restrict__ Vg_, const float* __restrict__ rb,
              const int* __restrict__ lengths, __half* __restrict__ out)
{
    extern __shared__ __align__(16) char smem_raw[];
    float*  bias_s = (float*)smem_raw;
    __half* Qs = (__half*)(smem_raw + 512);
    __half* Ks = (__half*)(smem_raw + 512 + 18432);
    __half* Vs = (__half*)(smem_raw + 512 + 36864);

    const int tid = threadIdx.x, lane = tid & 31, wr = tid >> 5;
    const int blk = blockIdx.x;
    const int qt = blk & 7, bh = blk >> 3;
    const int h = bh & (HH - 1), b = bh >> 3;
    const int q0 = qt * 128;
    const int len = lengths[b];
    const int nc = (len + 63) >> 6;

    if (tid < 127) bias_s[tid] = rb[h * 127 + tid] * 1.44269504f;

    const __half* Qg = Qg_ + ((size_t)bh * SS + q0) * DK;
    const __half* Kg = Kg_ + (size_t)bh * SS * DK;
    const __half* Vg = Vg_ + (size_t)bh * SS * DK;

#pragma unroll
    for (int i = 0; i < 4; i++) {
        int idx = tid + i * 256; int row = idx >> 3, c = idx & 7;
        cp_async16((uint32_t)__cvta_generic_to_shared(Qs + row * PITCH + c * 8),
                   Qg + (size_t)row * DK + c * 8);
    }
#pragma unroll
    for (int i = 0; i < 2; i++) {
        int idx = tid + i * 256; int row = idx >> 3, c = idx & 7;
        cp_async16((uint32_t)__cvta_generic_to_shared(Ks + row * PITCH + c * 8),
                   Kg + (size_t)row * DK + c * 8);
        cp_async16((uint32_t)__cvta_generic_to_shared(Vs + row * PITCH + c * 8),
                   Vg + (size_t)row * DK + c * 8);
    }
    cp_commit();

    float m0 = -1e30f, m1 = -1e30f, l0 = 0.f, l1 = 0.f;
    float oacc[8][4];
#pragma unroll
    for (int i = 0; i < 8; i++)
#pragma unroll
        for (int j = 0; j < 4; j++) oacc[i][j] = 0.f;
    uint32_t aQ[4][4];

    const int r = lane >> 2;
    const int qg0 = q0 + wr * 16 + r;
    const int qg1 = qg0 + 8;

    for (int cc = 0; cc < nc; cc++) {
        const int buf = cc & 1;
        if (cc + 1 < nc) {
            const int nb = buf ^ 1;
#pragma unroll
            for (int i = 0; i < 2; i++) {
                int idx = tid + i * 256; int row = idx >> 3, c = idx & 7;
                cp_async16((uint32_t)__cvta_generic_to_shared(Ks + nb * 64 * PITCH + row * PITCH + c * 8),
                           Kg + (size_t)((cc + 1) * 64 + row) * DK + c * 8);
                cp_async16((uint32_t)__cvta_generic_to_shared(Vs + nb * 64 * PITCH + row * PITCH + c * 8),
                           Vg + (size_t)((cc + 1) * 64 + row) * DK + c * 8);
            }
            cp_commit();
            cp_wait<1>();
        } else {
            cp_wait<0>();
        }
        __syncthreads();

        if (cc == 0) {
#pragma unroll
            for (int ks = 0; ks < 4; ks++) {
                const __half* p = Qs + (wr * 16 + ((lane >> 3) & 1) * 8 + (lane & 7)) * PITCH
                                  + ks * 16 + (lane >> 4) * 8;
                ldmx4(aQ[ks][0], aQ[ks][1], aQ[ks][2], aQ[ks][3],
                      (uint32_t)__cvta_generic_to_shared(p));
            }
        }

        const __half* kb = Ks + buf * 64 * PITCH;
        float sacc[8][4];
#pragma unroll
        for (int i = 0; i < 8; i++)
#pragma unroll
            for (int j = 0; j < 4; j++) sacc[i][j] = 0.f;
        const int g = lane >> 3, gi = lane & 7;
#pragma unroll
        for (int ks = 0; ks < 4; ks++) {
            uint32_t bK[8][2];
#pragma unroll
            for (int np = 0; np < 4; np++) {
                const __half* p = kb + (np * 16 + ((g >> 1) << 3) + gi) * PITCH
                                  + ks * 16 + ((g & 1) << 3);
                uint32_t t0, t1, t2, t3;
                ldmx4(t0, t1, t2, t3, (uint32_t)__cvta_generic_to_shared(p));
                bK[2 * np][0] = t0; bK[2 * np][1] = t1;
                bK[2 * np + 1][0] = t2; bK[2 * np + 1][1] = t3;
            }
#pragma unroll
            for (int nt = 0; nt < 8; nt++) mma16816(sacc[nt], aQ[ks], bK[nt]);
        }

        // ----- bias + mask fixup: full chunks skip the mask entirely -----
        const int kb0 = cc * 64;
        const bool full = (kb0 + 64 <= len);   // uniform across CTA
        float mc0 = -1e30f, mc1 = -1e30f;
        if (full) {
#pragma unroll
            for (int nt = 0; nt < 8; nt++) {
                const int k0i = kb0 + nt * 8 + 2 * (lane & 3);
#pragma unroll
                for (int e = 0; e < 4; e++) {
                    const int kk = k0i + (e & 1);
                    const int qq = (e < 2) ? qg0 : qg1;
                    int rel = min(63, max(-63, qq - kk)) + 63;
                    float val = sacc[nt][e] + bias_s[rel];
                    sacc[nt][e] = val;
                    if (e < 2) mc0 = fmaxf(mc0, val); else mc1 = fmaxf(mc1, val);
                }
            }
        } else {
#pragma unroll
            for (int nt = 0; nt < 8; nt++) {
                const int k0i = kb0 + nt * 8 + 2 * (lane & 3);
#pragma unroll
                for (int e = 0; e < 4; e++) {
                    const int kk = k0i + (e & 1);
                    const int qq = (e < 2) ? qg0 : qg1;
                    int rel = min(63, max(-63, qq - kk)) + 63;
                    float val = sacc[nt][e] + bias_s[rel];
                    if (kk >= len) val = -1e30f;
                    sacc[nt][e] = val;
                    if (e < 2) mc0 = fmaxf(mc0, val); else mc1 = fmaxf(mc1, val);
                }
            }
        }
        mc0 = fmaxf(mc0, __shfl_xor_sync(0xffffffffu, mc0, 1));
        mc0 = fmaxf(mc0, __shfl_xor_sync(0xffffffffu, mc0, 2));
        mc1 = fmaxf(mc1, __shfl_xor_sync(0xffffffffu, mc1, 1));
        mc1 = fmaxf(mc1, __shfl_xor_sync(0xffffffffu, mc1, 2));
        const float mn0 = fmaxf(m0, mc0), mn1 = fmaxf(m1, mc1);
        const float al0 = exp2p(m0 - mn0), al1 = exp2p(m1 - mn1);
        m0 = mn0; m1 = mn1;

        float ps0 = 0.f, ps1 = 0.f;
        uint32_t aP[4][4];
#pragma unroll
        for (int nt = 0; nt < 8; nt++) {
            float p0 = exp2p(sacc[nt][0] - mn0);
            float p1 = exp2p(sacc[nt][1] - mn0);
            float p2 = exp2p(sacc[nt][2] - mn1);
            float p3 = exp2p(sacc[nt][3] - mn1);
            ps0 += p0 + p1; ps1 += p2 + p3;
            uint32_t lo = f2h2(p0, p1), hi = f2h2(p2, p3);
            if ((nt & 1) == 0) { aP[nt >> 1][0] = lo; aP[nt >> 1][1] = hi; }
            else               { aP[nt >> 1][2] = lo; aP[nt >> 1][3] = hi; }
        }
        ps0 += __shfl_xor_sync(0xffffffffu, ps0, 1);
        ps0 += __shfl_xor_sync(0xffffffffu, ps0, 2);
        ps1 += __shfl_xor_sync(0xffffffffu, ps1, 1);
        ps1 += __shfl_xor_sync(0xffffffffu, ps1, 2);
        l0 = l0 * al0 + ps0;
        l1 = l1 * al1 + ps1;
#pragma unroll
        for (int nt = 0; nt < 8; nt++) {
            oacc[nt][0] *= al0; oacc[nt][1] *= al0;
            oacc[nt][2] *= al1; oacc[nt][3] *= al1;
        }

        const __half* vb = Vs + buf * 64 * PITCH;
#pragma unroll
        for (int kc = 0; kc < 4; kc++) {
            uint32_t bV[8][2];
#pragma unroll
            for (int np = 0; np < 4; np++) {
                const __half* p = vb + (kc * 16 + ((g & 1) << 3) + gi) * PITCH
                                  + np * 16 + ((g >> 1) << 3);
                uint32_t t0, t1, t2, t3;
                ldmx4t(t0, t1, t2, t3, (uint32_t)__cvta_generic_to_shared(p));
                bV[2 * np][0] = t0; bV[2 * np][1] = t1;
                bV[2 * np + 1][0] = t2; bV[2 * np + 1][1] = t3;
            }
#pragma unroll
            for (int nt = 0; nt < 8; nt++) mma16816(oacc[nt], aP[kc], bV[nt]);
        }
        __syncthreads();
    }

    const float inv0 = 1.f / l0, inv1 = 1.f / l1;
    __half* o0p = out + ((size_t)(b * SS + qg0)) * DD + h * DK + 2 * (lane & 3);
    __half* o1p = out + ((size_t)(b * SS + qg1)) * DD + h * DK + 2 * (lane & 3);
#pragma unroll
    for (int nt = 0; nt < 8; nt++) {
        *(__half2*)(o0p + nt * 8) = __floats2half2_rn(oacc[nt][0] * inv0, oacc[nt][1] * inv0);
        *(__half2*)(o1p + nt * 8) = __floats2half2_rn(oacc[nt][2] * inv1, oacc[nt][3] * inv1);
    }
}

// ================= host orchestration =================
#define G_PROJ gemm16<0, false, true,  false>
#define G_RES  gemm16<0, false, false, true >
#define G_QKV  gemm16<3, false, false, false>
#define G_FF1  gemm16<2, true,  false, false>

extern "C" void kernel_launch(void* const* d_in, const int* in_sizes, int n_in,
                              void* d_out, int out_size)
{
    const float* inputs  = (const float*)d_in[0];
    const int*   lengths = (const int*)  d_in[1];
    const float* W_in    = (const float*)d_in[2];
    const float* b_in    = (const float*)d_in[3];
    const float* Wq      = (const float*)d_in[4];
    const float* bq      = (const float*)d_in[5];
    const float* Wk      = (const float*)d_in[6];
    const float* bk      = (const float*)d_in[7];
    const float* Wv      = (const float*)d_in[8];
    const float* bv      = (const float*)d_in[9];
    const float* Wo      = (const float*)d_in[10];
    const float* bo      = (const float*)d_in[11];
    const float* rel_b   = (const float*)d_in[12];
    const float* W1      = (const float*)d_in[13];
    const float* b1      = (const float*)d_in[14];
    const float* W2      = (const float*)d_in[15];
    const float* b2      = (const float*)d_in[16];
    const float* g1      = (const float*)d_in[17];
    const float* be1     = (const float*)d_in[18];
    const float* g2      = (const float*)d_in[19];
    const float* be2     = (const float*)d_in[20];
    const float* gf      = (const float*)d_in[21];
    const float* bef     = (const float*)d_in[22];

    float *x, *bqkv, *pe;
    __half *qkv16, *h16, *in16, *ff16, *wi16, *wqkv16, *wo16, *w116, *w216;
    cudaGetSymbolAddress((void**)&x,      g_x);
    cudaGetSymbolAddress((void**)&qkv16,  g_qkv16);
    cudaGetSymbolAddress((void**)&h16,    g_h16);
    cudaGetSymbolAddress((void**)&in16,   g_in16);
    cudaGetSymbolAddress((void**)&ff16,   g_ff16);
    cudaGetSymbolAddress((void**)&wi16,   g_wi16);
    cudaGetSymbolAddress((void**)&wqkv16, g_wqkv16);
    cudaGetSymbolAddress((void**)&wo16,   g_wo16);
    cudaGetSymbolAddress((void**)&w116,   g_w116);
    cudaGetSymbolAddress((void**)&w216,   g_w216);
    cudaGetSymbolAddress((void**)&bqkv,   g_bqkv);
    cudaGetSymbolAddress((void**)&pe,     g_pe);

    cudaFuncSetAttribute(attn_mma, cudaFuncAttributeMaxDynamicSharedMemorySize, ATT_SMEM);
    cudaFuncSetAttribute(G_PROJ, cudaFuncAttributeMaxDynamicSharedMemorySize, GEMM_SMEM);
    cudaFuncSetAttribute(G_RES,  cudaFuncAttributeMaxDynamicSharedMemorySize, GEMM_SMEM);
    cudaFuncSetAttribute(G_QKV,  cudaFuncAttributeMaxDynamicSharedMemorySize, GEMM_SMEM);
    cudaFuncSetAttribute(G_FF1,  cudaFuncAttributeMaxDynamicSharedMemorySize, GEMM_SMEM);

    prep_kernel<<<PR_PE_END, 256>>>(inputs, W_in, Wq, Wk, Wv, Wo, W1, W2, bq, bk, bv,
                                    in16, wi16, wqkv16, wo16, w116, w216, bqkv, pe);

    const dim3 gD(DD / BN,   BS / BM);    // (4, 64)
    const dim3 gQ(NQKV / BN, BS / BM);    // (12, 64)
    const dim3 gF1(FF_ / BN, BS / BM);    // (16, 64)
    const float QSCALE = 0.125f * 1.44269504f;

    __half* q16 = qkv16;
    __half* k16 = qkv16 + (size_t)BS * DD;
    __half* v16 = qkv16 + 2 * (size_t)BS * DD;

    G_PROJ<<<gD, 128, GEMM_SMEM>>>(in16, wi16, b_in, nullptr, x, nullptr, INF_, DD, 1.0f, nullptr);

    for (int l = 0; l < LL; l++) {
        const __half* wqkv = wqkv16 + (size_t)l * NQKV * DD;
        const __half* wo = wo16 + (size_t)l * DD * DD;
        const __half* w1 = w116 + (size_t)l * DD * FF_;
        const __half* w2 = w216 + (size_t)l * FF_ * DD;

        ln_kernel<true><<<BS / 8, 256>>>(x, g1 + l * DD, be1 + l * DD, nullptr, h16);
        G_QKV<<<gQ, 128, GEMM_SMEM>>>(h16, wqkv, bqkv + l * NQKV, nullptr,
                                      nullptr, qkv16, DD, NQKV, QSCALE, lengths);

        attn_mma<<<BB * HH * (SS / 128), 256, ATT_SMEM>>>(q16, k16, v16,
                                                          rel_b + (size_t)l * HH * (2 * MM - 1),
                                                          lengths, h16);

        G_RES<<<gD, 128, GEMM_SMEM>>>(h16, wo, bo + l * DD, x, x, nullptr, DD, DD, 1.0f, nullptr);

        ln_kernel<true><<<BS / 8, 256>>>(x, g2 + l * DD, be2 + l * DD, nullptr, h16);
        G_FF1<<<gF1, 128, GEMM_SMEM>>>(h16, w1, b1 + l * FF_, nullptr,
                                       nullptr, ff16, DD, FF_, 1.0f, nullptr);
        G_RES<<<gD, 128, GEMM_SMEM>>>(ff16, w2, b2 + l * DD, x, x, nullptr, FF_, DD, 1.0f, nullptr);
    }

    ln_kernel<false><<<BS / 8, 256>>>(x, gf, bef, (float*)d_out, nullptr);
}